// round 11
// baseline (speedup 1.0000x reference)
#include <cuda_runtime.h>
#include <math.h>
#include <stdint.h>

// Problem constants (fixed by the reference)
#define N_NODES 50000
#define N_EDGES 800000
#define NE_TOT  850000      // edges + self loops
#define F_IN    256
#define HEADS   2
#define C1      200
#define HC1     400
#define C2      100
#define HC2     200
#define NGRAPH  64
#define SLOPE   0.2f
#define EPS_GN  1e-5f

#define SCAN_CHUNK 1024
#define NCHUNK ((N_NODES + SCAN_CHUNK - 1) / SCAN_CHUNK)   // 49

// ---------------- scratch: __device__ globals (alloc-free) ----------------
__device__ float4 g_xw1 [N_NODES * HC1 / 4];   // x @ W1
__device__ float4 g_c1  [N_NODES * HC1 / 4];   // h = relu(conv1 + b1)
__device__ float4 g_xw2 [N_NODES * HC2 / 4];   // h @ W2
__device__ float4 g_c2  [N_NODES * HC2 / 4];   // conv2 + b2
__device__ float2 g_als1[N_NODES], g_ald1[N_NODES];
__device__ float2 g_als2[N_NODES], g_ald2[N_NODES];
__device__ float  g_cnt [NGRAPH];
__device__ int    g_gstart[NGRAPH];
__device__ float  g_pool[NGRAPH * HC2];
// CSR by destination
__device__ int    g_src [NE_TOT], g_dst[NE_TOT];
__device__ int    g_deg [N_NODES], g_cur[N_NODES];
__device__ int    g_off [N_NODES + 1];
__device__ int    g_part[NCHUNK];
__device__ int    g_ssrc[NE_TOT];              // src ids sorted by dst
__device__ int    g_batch[N_NODES];
__device__ int    g_is64;

// ---------------- detect input index width (int64 downcast-view vs int32) ----------------
__global__ void detect_kernel(const int* __restrict__ ei)
{
    if (threadIdx.x == 0 && blockIdx.x == 0) {
        int any = 0;
        for (int k = 0; k < 256; k++) any |= ei[2 * k + 1];
        g_is64 = (any == 0) ? 1 : 0;
    }
}

// ---------------- decode indices to int32, append self loops; zero counters ----------------
__global__ void convert_idx_kernel(const int* __restrict__ ei, const int* __restrict__ batch)
{
    int i = blockIdx.x * blockDim.x + threadIdx.x;
    int is64 = g_is64;
    if (i < NE_TOT) {
        if (i < N_EDGES) {
            g_src[i] = is64 ? ei[2 * i]             : ei[i];
            g_dst[i] = is64 ? ei[2 * (N_EDGES + i)] : ei[N_EDGES + i];
        } else {
            int n = i - N_EDGES;
            g_src[i] = n; g_dst[i] = n;
        }
    }
    if (i < N_NODES) {
        g_batch[i] = is64 ? batch[2 * i] : batch[i];
        g_deg[i] = 0; g_cur[i] = 0;
    }
    if (i < NGRAPH) g_cnt[i] = 0.f;
}

// ---------------- CSR build ----------------
__global__ void csr_count_kernel()
{
    int i = blockIdx.x * blockDim.x + threadIdx.x;
    if (i >= NE_TOT) return;
    atomicAdd(&g_deg[g_dst[i]], 1);
}

__global__ void scan1_kernel()
{
    __shared__ int buf[SCAN_CHUNK];
    int tid = threadIdx.x;
    int i = blockIdx.x * SCAN_CHUNK + tid;
    int v = (i < N_NODES) ? g_deg[i] : 0;
    buf[tid] = v;
    __syncthreads();
    for (int off = 1; off < SCAN_CHUNK; off <<= 1) {
        int t = (tid >= off) ? buf[tid - off] : 0;
        __syncthreads();
        buf[tid] += t;
        __syncthreads();
    }
    if (i < N_NODES) g_off[i] = buf[tid] - v;
    if (tid == SCAN_CHUNK - 1) g_part[blockIdx.x] = buf[tid];
}

__global__ void scan2_kernel()
{
    if (threadIdx.x == 0 && blockIdx.x == 0) {
        int run = 0;
        for (int b = 0; b < NCHUNK; b++) { int t = g_part[b]; g_part[b] = run; run += t; }
        g_off[N_NODES] = run;
    }
}

__global__ void scan3_kernel()
{
    int i = blockIdx.x * blockDim.x + threadIdx.x;
    if (i < N_NODES) g_off[i] += g_part[i >> 10];
}

__global__ void csr_fill_kernel()
{
    int i = blockIdx.x * blockDim.x + threadIdx.x;
    if (i >= NE_TOT) return;
    int d = g_dst[i];
    int pos = atomicAdd(&g_cur[d], 1);
    g_ssrc[g_off[d] + pos] = g_src[i];
}

// ---------------- graph node counts + start offsets (batch is sorted) ----------------
__global__ void counts_kernel()
{
    int n = blockIdx.x * blockDim.x + threadIdx.x;
    if (n >= N_NODES) return;
    atomicAdd(&g_cnt[g_batch[n]], 1.f);
}

__global__ void graph_offsets_kernel()
{
    if (threadIdx.x == 0 && blockIdx.x == 0) {
        int off = 0;
        for (int g = 0; g < NGRAPH; g++) { g_gstart[g] = off; off += (int)g_cnt[g]; }
    }
}

// ---------------- TF32 helpers ----------------
__device__ __forceinline__ uint32_t f2tf32(float f)
{
    uint32_t u;
    asm("cvt.rna.tf32.f32 %0, %1;" : "=r"(u) : "f"(f));
    return u;
}

__device__ __forceinline__ void mma_tf32(float* c, const uint32_t* a, const uint32_t* b)
{
    asm volatile(
        "mma.sync.aligned.m16n8k8.row.col.f32.tf32.tf32.f32 "
        "{%0,%1,%2,%3}, {%4,%5,%6,%7}, {%8,%9}, {%0,%1,%2,%3};"
        : "+f"(c[0]), "+f"(c[1]), "+f"(c[2]), "+f"(c[3])
        : "r"(a[0]), "r"(a[1]), "r"(a[2]), "r"(a[3]), "r"(b[0]), "r"(b[1]));
}

// ---------------- GEMM: C[M,Nc] = A[M,K] @ B[K,Nc], tf32 tensor cores, 3x-compensated ----------------
// 128x64 block tile, BK=8 double-buffered, 256 threads (8 warps, 2m x 4n, warp tile 64x16).
#define BM 128
#define BN 64
#define BK 8
#define ASTRIDE 136   // % 32 == 8 -> conflict-free frag loads
#define BSTRIDE 72    // % 32 == 8

template<int LAYER>
__global__ __launch_bounds__(256) void gemm_kernel(
    const float* __restrict__ Aext, const float* __restrict__ B)
{
    constexpr int M  = N_NODES;
    constexpr int Nc = (LAYER == 1) ? HC1 : HC2;
    constexpr int K  = (LAYER == 1) ? F_IN : HC1;
    const float* __restrict__ A = (LAYER == 1) ? Aext : (const float*)g_c1;
    float* __restrict__ C       = (LAYER == 1) ? (float*)g_xw1 : (float*)g_xw2;

    __shared__ float As[2][BK][ASTRIDE];
    __shared__ float Bs[2][BK][BSTRIDE];

    int tid  = threadIdx.x;
    int warp = tid >> 5;
    int lane = tid & 31;
    int gid  = lane >> 2;        // group id (0..7)
    int tig  = lane & 3;         // thread in group (0..3)

    int row0 = blockIdx.y * BM;
    int col0 = blockIdx.x * BN;
    int wm0  = (warp >> 2) * 64; // warp m offset within block (0 or 64)
    int wn0  = (warp & 3) * 16;  // warp n offset within block (0,16,32,48)

    // staging coords
    int am = tid >> 1, af = tid & 1;          // A: row am, float4 slot af
    int agm = row0 + am;
    int bkk = tid >> 4, bn4 = tid & 15;       // B (tid<128): k row, float4 col
    int bgn = col0 + bn4 * 4;

    float acc[4][2][4];                       // [mf][nf][reg]
#pragma unroll
    for (int i = 0; i < 4; i++)
#pragma unroll
        for (int j = 0; j < 2; j++)
#pragma unroll
            for (int r = 0; r < 4; r++) acc[i][j][r] = 0.f;

    // prologue: stage 0
    {
        float4 av = make_float4(0.f, 0.f, 0.f, 0.f);
        if (agm < M) av = *(const float4*)&A[(size_t)agm * K + af * 4];
        As[0][af * 4 + 0][am] = av.x;
        As[0][af * 4 + 1][am] = av.y;
        As[0][af * 4 + 2][am] = av.z;
        As[0][af * 4 + 3][am] = av.w;
        if (tid < 128) {
            float4 bv = make_float4(0.f, 0.f, 0.f, 0.f);
            if (bgn + 4 <= Nc) bv = *(const float4*)&B[(size_t)bkk * Nc + bgn];
            *(float4*)&Bs[0][bkk][bn4 * 4] = bv;
        }
    }
    __syncthreads();

    constexpr int NSTEP = K / BK;
    int buf = 0;
    for (int s = 0; s < NSTEP; s++) {
        float4 av, bv;
        bool has_next = (s + 1 < NSTEP);
        if (has_next) {
            int k0 = (s + 1) * BK;
            av = make_float4(0.f, 0.f, 0.f, 0.f);
            if (agm < M) av = *(const float4*)&A[(size_t)agm * K + k0 + af * 4];
            bv = make_float4(0.f, 0.f, 0.f, 0.f);
            if (tid < 128 && bgn + 4 <= Nc) bv = *(const float4*)&B[(size_t)(k0 + bkk) * Nc + bgn];
        }

        // load fragments + tf32 hi/lo split
        uint32_t ahi[4][4], alo[4][4], bhi[2][2], blo[2][2];
#pragma unroll
        for (int mf = 0; mf < 4; mf++) {
            int m = wm0 + mf * 16 + gid;
            float f0 = As[buf][tig][m];
            float f1 = As[buf][tig][m + 8];
            float f2 = As[buf][tig + 4][m];
            float f3 = As[buf][tig + 4][m + 8];
            ahi[mf][0] = f2tf32(f0); alo[mf][0] = f2tf32(f0 - __uint_as_float(ahi[mf][0]));
            ahi[mf][1] = f2tf32(f1); alo[mf][1] = f2tf32(f1 - __uint_as_float(ahi[mf][1]));
            ahi[mf][2] = f2tf32(f2); alo[mf][2] = f2tf32(f2 - __uint_as_float(ahi[mf][2]));
            ahi[mf][3] = f2tf32(f3); alo[mf][3] = f2tf32(f3 - __uint_as_float(ahi[mf][3]));
        }
#pragma unroll
        for (int nf = 0; nf < 2; nf++) {
            int n = wn0 + nf * 8 + gid;
            float f0 = Bs[buf][tig][n];
            float f1 = Bs[buf][tig + 4][n];
            bhi[nf][0] = f2tf32(f0); blo[nf][0] = f2tf32(f0 - __uint_as_float(bhi[nf][0]));
            bhi[nf][1] = f2tf32(f1); blo[nf][1] = f2tf32(f1 - __uint_as_float(bhi[nf][1]));
        }

        // 3x-compensated MMAs
#pragma unroll
        for (int mf = 0; mf < 4; mf++)
#pragma unroll
            for (int nf = 0; nf < 2; nf++) {
                mma_tf32(acc[mf][nf], ahi[mf], bhi[nf]);
                mma_tf32(acc[mf][nf], alo[mf], bhi[nf]);
                mma_tf32(acc[mf][nf], ahi[mf], blo[nf]);
            }

        if (has_next) {
            int nb = buf ^ 1;
            As[nb][af * 4 + 0][am] = av.x;
            As[nb][af * 4 + 1][am] = av.y;
            As[nb][af * 4 + 2][am] = av.z;
            As[nb][af * 4 + 3][am] = av.w;
            if (tid < 128) *(float4*)&Bs[nb][bkk][bn4 * 4] = bv;
        }
        __syncthreads();
        buf ^= 1;
    }

    // epilogue: c0,c1 at (gid, tig*2), c2,c3 at (gid+8, tig*2)
#pragma unroll
    for (int mf = 0; mf < 4; mf++) {
#pragma unroll
        for (int nf = 0; nf < 2; nf++) {
            int gm = row0 + wm0 + mf * 16 + gid;
            int gn = col0 + wn0 + nf * 8 + tig * 2;
            if (gn + 2 <= Nc) {
                if (gm < M)
                    *(float2*)&C[(size_t)gm * Nc + gn] = make_float2(acc[mf][nf][0], acc[mf][nf][1]);
                if (gm + 8 < M)
                    *(float2*)&C[(size_t)(gm + 8) * Nc + gn] = make_float2(acc[mf][nf][2], acc[mf][nf][3]);
            }
        }
    }
}

// ---------------- per-node attention logits: one thread per (node, head) ----------------
template<int LAYER>
__global__ void attn_logits_kernel(const float* __restrict__ asrc, const float* __restrict__ adst)
{
    constexpr int HC = (LAYER == 1) ? HC1 : HC2;
    constexpr int C  = (LAYER == 1) ? C1 : C2;
    const float* __restrict__ xw = (LAYER == 1) ? (const float*)g_xw1 : (const float*)g_xw2;
    float2* __restrict__ als = (LAYER == 1) ? g_als1 : g_als2;
    float2* __restrict__ ald = (LAYER == 1) ? g_ald1 : g_ald2;

    int i = blockIdx.x * blockDim.x + threadIdx.x;
    if (i >= N_NODES * HEADS) return;
    int n = i >> 1, h = i & 1;
    const float4* row = (const float4*)(xw + (size_t)n * HC + h * C);
    const float4* va  = (const float4*)(asrc + h * C);
    const float4* vb  = (const float4*)(adst + h * C);
    float s = 0.f, t = 0.f;
#pragma unroll 5
    for (int c = 0; c < C / 4; c++) {
        float4 r = row[c], a = va[c], b = vb[c];
        s += r.x * a.x + r.y * a.y + r.z * a.z + r.w * a.w;
        t += r.x * b.x + r.y * b.y + r.z * b.z + r.w * b.w;
    }
    ((float*)als)[i] = s;
    ((float*)ald)[i] = t;
}

// ---------------- fused attention aggregate: 2 warps per destination node ----------------
template<int LAYER>
__global__ __launch_bounds__(256) void attn_aggr_kernel(const float* __restrict__ bias)
{
    constexpr int HC4   = ((LAYER == 1) ? HC1 : HC2) / 4;   // 100 / 50
    constexpr int C4    = ((LAYER == 1) ? C1 : C2) / 4;     // 50 / 25
    constexpr int PART4 = HC4 / 2;                          // 50 / 25 float4 per warp
    constexpr int NACC  = (PART4 + 31) / 32;                // 2 / 1
    const float2* __restrict__ als = (LAYER == 1) ? g_als1 : g_als2;
    const float2* __restrict__ ald = (LAYER == 1) ? g_ald1 : g_ald2;
    const float4* __restrict__ xw  = (LAYER == 1) ? g_xw1 : g_xw2;
    float4* __restrict__ outv      = (LAYER == 1) ? g_c1 : g_c2;

    int w = (blockIdx.x * blockDim.x + threadIdx.x) >> 5;
    int d    = w >> 1;
    int part = w & 1;
    if (d >= N_NODES) return;
    int lane = threadIdx.x & 31;
    int off0 = g_off[d], off1 = g_off[d + 1];
    float2 ad = ald[d];

    // pass A: softmax denominator (warp reduction)
    float z0 = 0.f, z1 = 0.f;
    for (int t = off0 + lane; t < off1; t += 32) {
        float2 as_ = als[g_ssrc[t]];
        float e0 = as_.x + ad.x; e0 = (e0 > 0.f) ? e0 : SLOPE * e0;
        float e1 = as_.y + ad.y; e1 = (e1 > 0.f) ? e1 : SLOPE * e1;
        z0 += __expf(e0);
        z1 += __expf(e1);
    }
#pragma unroll
    for (int o = 16; o; o >>= 1) {
        z0 += __shfl_xor_sync(0xffffffffu, z0, o);
        z1 += __shfl_xor_sync(0xffffffffu, z1, o);
    }
    float inv0 = 1.f / z0, inv1 = 1.f / z1;

    // pass B: gather-accumulate, 2-edge unroll
    float4 acc[NACC];
#pragma unroll
    for (int r = 0; r < NACC; r++) acc[r] = make_float4(0.f, 0.f, 0.f, 0.f);

    int cbase = part * PART4;
    int t = off0;
    for (; t + 1 < off1; t += 2) {
        int s0 = g_ssrc[t], s1 = g_ssrc[t + 1];
        float2 as0 = als[s0], as1 = als[s1];
        float e00 = as0.x + ad.x; e00 = (e00 > 0.f) ? e00 : SLOPE * e00;
        float e01 = as0.y + ad.y; e01 = (e01 > 0.f) ? e01 : SLOPE * e01;
        float e10 = as1.x + ad.x; e10 = (e10 > 0.f) ? e10 : SLOPE * e10;
        float e11 = as1.y + ad.y; e11 = (e11 > 0.f) ? e11 : SLOPE * e11;
        float a00 = __expf(e00) * inv0, a01 = __expf(e01) * inv1;
        float a10 = __expf(e10) * inv0, a11 = __expf(e11) * inv1;
        const float4* xr0 = xw + (size_t)s0 * HC4;
        const float4* xr1 = xw + (size_t)s1 * HC4;
#pragma unroll
        for (int r = 0; r < NACC; r++) {
            int c4 = cbase + lane + 32 * r;
            if (lane + 32 * r < PART4) {
                float aa = (c4 < C4) ? a00 : a01;
                float ab = (c4 < C4) ? a10 : a11;
                float4 v0 = __ldg(&xr0[c4]);
                float4 v1 = __ldg(&xr1[c4]);
                acc[r].x += aa * v0.x + ab * v1.x;
                acc[r].y += aa * v0.y + ab * v1.y;
                acc[r].z += aa * v0.z + ab * v1.z;
                acc[r].w += aa * v0.w + ab * v1.w;
            }
        }
    }
    if (t < off1) {
        int s0 = g_ssrc[t];
        float2 as0 = als[s0];
        float e00 = as0.x + ad.x; e00 = (e00 > 0.f) ? e00 : SLOPE * e00;
        float e01 = as0.y + ad.y; e01 = (e01 > 0.f) ? e01 : SLOPE * e01;
        float a00 = __expf(e00) * inv0, a01 = __expf(e01) * inv1;
        const float4* xr0 = xw + (size_t)s0 * HC4;
#pragma unroll
        for (int r = 0; r < NACC; r++) {
            int c4 = cbase + lane + 32 * r;
            if (lane + 32 * r < PART4) {
                float aa = (c4 < C4) ? a00 : a01;
                float4 v0 = __ldg(&xr0[c4]);
                acc[r].x += aa * v0.x; acc[r].y += aa * v0.y;
                acc[r].z += aa * v0.z; acc[r].w += aa * v0.w;
            }
        }
    }

    // epilogue: bias (+relu for layer 1), single store
    const float4* b4 = (const float4*)bias;
#pragma unroll
    for (int r = 0; r < NACC; r++) {
        int c4 = cbase + lane + 32 * r;
        if (lane + 32 * r < PART4) {
            float4 b = b4[c4];
            float4 v;
            if (LAYER == 1) {
                v.x = fmaxf(acc[r].x + b.x, 0.f);
                v.y = fmaxf(acc[r].y + b.y, 0.f);
                v.z = fmaxf(acc[r].z + b.z, 0.f);
                v.w = fmaxf(acc[r].w + b.w, 0.f);
            } else {
                v.x = acc[r].x + b.x; v.y = acc[r].y + b.y;
                v.z = acc[r].z + b.z; v.w = acc[r].w + b.w;
            }
            outv[(size_t)d * HC4 + c4] = v;
        }
    }
}

// ---------------- fused GraphNorm + relu + mean-pool ----------------
__global__ __launch_bounds__(128) void graphnorm_kernel(
    const float* __restrict__ gn_ms, const float* __restrict__ gn_w, const float* __restrict__ gn_b)
{
    int g = blockIdx.x;
    int c = blockIdx.y * (HC2 / 2) + threadIdx.x;
    if (threadIdx.x >= HC2 / 2) return;
    int n0 = g_gstart[g];
    float cntf = g_cnt[g];
    int n1 = n0 + (int)cntf;
    const float* h = (const float*)g_c2;

    float s0 = 0.f, s1 = 0.f, s2 = 0.f, s3 = 0.f;
    int n = n0;
    for (; n + 3 < n1; n += 4) {
        s0 += h[(size_t)(n + 0) * HC2 + c];
        s1 += h[(size_t)(n + 1) * HC2 + c];
        s2 += h[(size_t)(n + 2) * HC2 + c];
        s3 += h[(size_t)(n + 3) * HC2 + c];
    }
    for (; n < n1; n++) s0 += h[(size_t)n * HC2 + c];
    float mean_ms = ((s0 + s1) + (s2 + s3)) / cntf * gn_ms[c];

    float v0 = 0.f, v1 = 0.f, v2 = 0.f, v3 = 0.f;
    n = n0;
    for (; n + 3 < n1; n += 4) {
        float t0 = h[(size_t)(n + 0) * HC2 + c] - mean_ms;
        float t1 = h[(size_t)(n + 1) * HC2 + c] - mean_ms;
        float t2 = h[(size_t)(n + 2) * HC2 + c] - mean_ms;
        float t3 = h[(size_t)(n + 3) * HC2 + c] - mean_ms;
        v0 += t0 * t0; v1 += t1 * t1; v2 += t2 * t2; v3 += t3 * t3;
    }
    for (; n < n1; n++) { float t = h[(size_t)n * HC2 + c] - mean_ms; v0 += t * t; }
    float scale = rsqrtf(((v0 + v1) + (v2 + v3)) / cntf + EPS_GN);

    float w = gn_w[c], b = gn_b[c];
    float p0 = 0.f, p1 = 0.f, p2 = 0.f, p3 = 0.f;
    n = n0;
    for (; n + 3 < n1; n += 4) {
        p0 += fmaxf(w * ((h[(size_t)(n + 0) * HC2 + c] - mean_ms) * scale) + b, 0.f);
        p1 += fmaxf(w * ((h[(size_t)(n + 1) * HC2 + c] - mean_ms) * scale) + b, 0.f);
        p2 += fmaxf(w * ((h[(size_t)(n + 2) * HC2 + c] - mean_ms) * scale) + b, 0.f);
        p3 += fmaxf(w * ((h[(size_t)(n + 3) * HC2 + c] - mean_ms) * scale) + b, 0.f);
    }
    for (; n < n1; n++)
        p0 += fmaxf(w * ((h[(size_t)n * HC2 + c] - mean_ms) * scale) + b, 0.f);
    g_pool[g * HC2 + c] = (p0 + p1) + (p2 + p3);
}

// ---------------- final: logits = (pool/cnt) @ lin_w + lin_b; sigmoid ----------------
__global__ void final_kernel(const float* __restrict__ lin_w, const float* __restrict__ lin_b,
                             float* __restrict__ out)
{
    int t = threadIdx.x;
    if (t >= NGRAPH * 2) return;
    int g = t / 2, k = t % 2;
    float acc = 0.f;
#pragma unroll 8
    for (int c = 0; c < HC2; c++)
        acc += g_pool[g * HC2 + c] * lin_w[c * 2 + k];
    float logit = acc / g_cnt[g] + lin_b[k];
    out[g * 2 + k] = 1.f / (1.f + __expf(-logit));
}

// ---------------- launch ----------------
extern "C" void kernel_launch(void* const* d_in, const int* in_sizes, int n_in,
                              void* d_out, int out_size)
{
    const float* x      = (const float*)d_in[0];
    const int*   ei     = (const int*)d_in[1];
    const int*   batch  = (const int*)d_in[2];
    const float* W1     = (const float*)d_in[3];
    const float* a_src1 = (const float*)d_in[4];
    const float* a_dst1 = (const float*)d_in[5];
    const float* b1     = (const float*)d_in[6];
    const float* W2     = (const float*)d_in[7];
    const float* a_src2 = (const float*)d_in[8];
    const float* a_dst2 = (const float*)d_in[9];
    const float* b2     = (const float*)d_in[10];
    const float* gn_w   = (const float*)d_in[11];
    const float* gn_b   = (const float*)d_in[12];
    const float* gn_ms  = (const float*)d_in[13];
    const float* lin_w  = (const float*)d_in[14];
    const float* lin_b  = (const float*)d_in[15];
    float*       out    = (float*)d_out;

    // index decode + CSR build + graph offsets
    detect_kernel<<<1, 32>>>(ei);
    convert_idx_kernel<<<(NE_TOT + 255) / 256, 256>>>(ei, batch);
    csr_count_kernel<<<(NE_TOT + 255) / 256, 256>>>();
    scan1_kernel<<<NCHUNK, SCAN_CHUNK>>>();
    scan2_kernel<<<1, 32>>>();
    scan3_kernel<<<(N_NODES + 255) / 256, 256>>>();
    csr_fill_kernel<<<(NE_TOT + 255) / 256, 256>>>();
    counts_kernel<<<(N_NODES + 255) / 256, 256>>>();
    graph_offsets_kernel<<<1, 32>>>();

    // ---- layer 1 ----
    {
        dim3 grid((HC1 + BN - 1) / BN, (N_NODES + BM - 1) / BM);
        gemm_kernel<1><<<grid, 256>>>(x, W1);
    }
    attn_logits_kernel<1><<<(N_NODES * HEADS + 255) / 256, 256>>>(a_src1, a_dst1);
    attn_aggr_kernel<1><<<(N_NODES * 2 * 32 + 255) / 256, 256>>>(b1);

    // ---- layer 2 ----
    {
        dim3 grid((HC2 + BN - 1) / BN, (N_NODES + BM - 1) / BM);
        gemm_kernel<2><<<grid, 256>>>(nullptr, W2);
    }
    attn_logits_kernel<2><<<(N_NODES * HEADS + 255) / 256, 256>>>(a_src2, a_dst2);
    attn_aggr_kernel<2><<<(N_NODES * 2 * 32 + 255) / 256, 256>>>(b2);

    // ---- graphnorm + pool + head ----
    {
        dim3 grid(NGRAPH, 2);
        graphnorm_kernel<<<grid, 128>>>(gn_ms, gn_w, gn_b);
    }
    final_kernel<<<1, 128>>>(lin_w, lin_b, out);
}